// round 1
// baseline (speedup 1.0000x reference)
#include <cuda_runtime.h>
#include <math.h>

// Problem constants
#define B_  32
#define C_  512
#define T_  4000
#define NV_ 1000          // T/4 float4s
#define H4C 2048          // 4*C (stats width)

// ---------------- scratch (device globals; no allocation allowed) -----------
__device__ float g_statsT[H4C * B_];          // [2048][32]  feature-major, batch=lane
__device__ float g_hT[C_ * B_];               // [512][32]
__device__ float g_p1[16 * C_ * B_];          // gemm1 K-split partials: 16 splits
__device__ float g_p2[4 * 2 * C_ * B_];       // gemm2 K-split partials: 4 splits x 1024 rows

// ---------------- kernel 1: fused add + 4-moment reduction ------------------
__global__ __launch_bounds__(256) void stats_kernel(
    const float* __restrict__ xa, const float* __restrict__ xb)
{
    int c = blockIdx.x;
    int b = blockIdx.y;
    size_t base = ((size_t)(b * C_ + c)) * T_;
    const float4* a4 = reinterpret_cast<const float4*>(xa + base);
    const float4* b4 = reinterpret_cast<const float4*>(xb + base);

    float s1 = 0.f, s2 = 0.f, s3 = 0.f, s4 = 0.f;
    for (int i = threadIdx.x; i < NV_; i += 256) {
        float4 av = a4[i];
        float4 bv = b4[i];
        float xs0 = av.x + bv.x, xs1 = av.y + bv.y, xs2 = av.z + bv.z, xs3 = av.w + bv.w;
        float xv[4] = {xs0, xs1, xs2, xs3};
        #pragma unroll
        for (int q = 0; q < 4; q++) {
            float x = xv[q];
            float x2 = x * x;
            s1 += x;
            s2 = fmaf(x, x, s2);
            s3 = fmaf(x2, x, s3);
            s4 = fmaf(x2, x2, s4);
        }
    }
    // warp reduce
    #pragma unroll
    for (int off = 16; off > 0; off >>= 1) {
        s1 += __shfl_down_sync(0xffffffffu, s1, off);
        s2 += __shfl_down_sync(0xffffffffu, s2, off);
        s3 += __shfl_down_sync(0xffffffffu, s3, off);
        s4 += __shfl_down_sync(0xffffffffu, s4, off);
    }
    __shared__ float red[8][4];
    int w = threadIdx.x >> 5;
    if ((threadIdx.x & 31) == 0) {
        red[w][0] = s1; red[w][1] = s2; red[w][2] = s3; red[w][3] = s4;
    }
    __syncthreads();
    if (threadIdx.x == 0) {
        float t1 = 0.f, t2 = 0.f, t3 = 0.f, t4 = 0.f;
        #pragma unroll
        for (int i = 0; i < 8; i++) {
            t1 += red[i][0]; t2 += red[i][1]; t3 += red[i][2]; t4 += red[i][3];
        }
        const float Tf = (float)T_;
        float m  = t1 / Tf;
        float m2 = m * m;
        float sc2 = t2 - t1 * m;                       // sum centered^2
        float var = fmaxf(sc2 / (Tf - 1.0f), 0.f);     // unbiased
        float sd  = sqrtf(var);
        float d   = fmaxf(sd, 0.01f);                  // EPS clamp
        float sc3 = t3 - 3.f * m * t2 + 2.f * Tf * m * m2;
        float sc4 = t4 - 4.f * m * t3 + 6.f * m2 * t2 - 3.f * Tf * m2 * m2;
        float d3inv = 1.f / (Tf * d * d * d);
        float skew = sc3 * d3inv;
        float kurt = sc4 * d3inv / d;
        g_statsT[(c)            * B_ + b] = m;
        g_statsT[(C_ + c)       * B_ + b] = sd;
        g_statsT[(2 * C_ + c)   * B_ + b] = skew;
        g_statsT[(3 * C_ + c)   * B_ + b] = kurt;
    }
}

// ---------------- generic mini-GEMM: out[r][b] partials = A[r][:K] . xT[:K][b]
// Block: 32 output rows x 32 batch, K-chunk of 128 per blockIdx.y.
// Writes partial to outP[blockIdx.y * rows * 32 + r*32 + b] (deterministic,
// reduced later in fixed order).
__device__ __forceinline__ void gemm_tile(
    const float* __restrict__ A, const float* __restrict__ xT,
    float* __restrict__ outP, int K, int rows)
{
    __shared__ float sA[32 * 128];
    __shared__ float sX[128 * 32];
    int j0 = blockIdx.x * 32;
    int i0 = blockIdx.y * 128;
    int tid = threadIdx.x;

    for (int idx = tid; idx < 32 * 128; idx += 256) {
        int jj = idx >> 7;
        int k  = idx & 127;
        sA[idx] = A[(size_t)(j0 + jj) * K + i0 + k];
    }
    for (int idx = tid; idx < 128 * 32; idx += 256)
        sX[idx] = xT[i0 * B_ + idx];
    __syncthreads();

    int b  = tid & 31;
    int jb = (tid >> 5) * 4;     // 8 warps * 4 rows = 32 rows
    float a0 = 0.f, a1 = 0.f, a2 = 0.f, a3 = 0.f;
    #pragma unroll 8
    for (int k = 0; k < 128; k++) {
        float s = sX[k * 32 + b];                 // lanes: distinct banks
        a0 = fmaf(sA[(jb + 0) * 128 + k], s, a0); // broadcast loads
        a1 = fmaf(sA[(jb + 1) * 128 + k], s, a1);
        a2 = fmaf(sA[(jb + 2) * 128 + k], s, a2);
        a3 = fmaf(sA[(jb + 3) * 128 + k], s, a3);
    }
    size_t obase = (size_t)blockIdx.y * rows * B_ + (size_t)(j0 + jb) * B_ + b;
    outP[obase + 0 * B_] = a0;
    outP[obase + 1 * B_] = a1;
    outP[obase + 2 * B_] = a2;
    outP[obase + 3 * B_] = a3;
}

__global__ __launch_bounds__(256) void gemm1_kernel(const float* __restrict__ W1)
{
    gemm_tile(W1, g_statsT, g_p1, H4C, C_);
}

__global__ __launch_bounds__(256) void reduce1_kernel(const float* __restrict__ b1)
{
    int idx = blockIdx.x * blockDim.x + threadIdx.x;   // over 512*32
    if (idx >= C_ * B_) return;
    float acc = b1[idx >> 5];
    #pragma unroll
    for (int sp = 0; sp < 16; sp++)
        acc += g_p1[sp * (C_ * B_) + idx];
    g_hT[idx] = acc;
}

__global__ __launch_bounds__(256) void gemm2_kernel(const float* __restrict__ W2)
{
    gemm_tile(W2, g_hT, g_p2, C_, 2 * C_);
}

// ---------------- kernel 5: gate reduce + softmax + weighted combine --------
__global__ __launch_bounds__(256) void apply_kernel(
    const float* __restrict__ xa, const float* __restrict__ xb,
    const float* __restrict__ b2, float* __restrict__ out)
{
    int c = blockIdx.x;
    int b = blockIdx.y;

    // finish gate GEMM reduction (fixed order) + bias, redundantly per thread
    float s0 = b2[c];
    float s1 = b2[C_ + c];
    #pragma unroll
    for (int sp = 0; sp < 4; sp++) {
        s0 += g_p2[(size_t)sp * (2 * C_ * B_) + (size_t)c * B_ + b];
        s1 += g_p2[(size_t)sp * (2 * C_ * B_) + (size_t)(C_ + c) * B_ + b];
    }
    float mx = fmaxf(s0, s1);
    float e0 = __expf(s0 - mx);
    float e1 = __expf(s1 - mx);
    float inv = 1.f / (e0 + e1);
    float g0 = e0 * inv;
    float g1 = e1 * inv;

    size_t base = ((size_t)(b * C_ + c)) * T_;
    const float4* a4 = reinterpret_cast<const float4*>(xa + base);
    const float4* b4 = reinterpret_cast<const float4*>(xb + base);
    float4* o4 = reinterpret_cast<float4*>(out + base);
    for (int i = threadIdx.x; i < NV_; i += 256) {
        float4 av = a4[i];
        float4 bv = b4[i];
        float4 r;
        r.x = fmaf(av.x, g0, bv.x * g1);
        r.y = fmaf(av.y, g0, bv.y * g1);
        r.z = fmaf(av.z, g0, bv.z * g1);
        r.w = fmaf(av.w, g0, bv.w * g1);
        o4[i] = r;
    }
}

// ---------------- launcher --------------------------------------------------
extern "C" void kernel_launch(void* const* d_in, const int* in_sizes, int n_in,
                              void* d_out, int out_size)
{
    const float* xa = (const float*)d_in[0];
    const float* xb = (const float*)d_in[1];
    const float* W1 = (const float*)d_in[2];
    const float* b1 = (const float*)d_in[3];
    const float* W2 = (const float*)d_in[4];
    const float* b2 = (const float*)d_in[5];
    float* out = (float*)d_out;

    stats_kernel<<<dim3(C_, B_), 256>>>(xa, xb);
    gemm1_kernel<<<dim3(C_ / 32, H4C / 128), 256>>>(W1);          // 16 x 16
    reduce1_kernel<<<(C_ * B_ + 255) / 256, 256>>>(b1);           // 64 blocks
    gemm2_kernel<<<dim3(2 * C_ / 32, C_ / 128), 256>>>(W2);       // 32 x 4
    apply_kernel<<<dim3(C_, B_), 256>>>(xa, xb, b2, out);
}

// round 2
// speedup vs baseline: 1.0299x; 1.0299x over previous
#include <cuda_runtime.h>
#include <math.h>

// Problem constants
#define B_  32
#define C_  512
#define T_  4000
#define NV_ 1000          // T/4 float4s
#define H4C 2048          // 4*C (stats width)
#define SAP 36            // padded sA row stride (floats): 144B, 16B-aligned, 4-way store conflict only

// ---------------- scratch (device globals; no allocation allowed) -----------
__device__ float g_statsT[H4C * B_];          // [2048][32]  feature-major, batch=lane
__device__ float g_hT[C_ * B_];               // [512][32]
__device__ float g_p1[16 * C_ * B_];          // gemm1 K-split partials: 16 splits
__device__ float g_p2[4 * 2 * C_ * B_];       // gemm2 K-split partials: 4 splits x 1024 rows

// ---------------- kernel 1: fused add + 4-moment reduction ------------------
__global__ __launch_bounds__(256) void stats_kernel(
    const float* __restrict__ xa, const float* __restrict__ xb)
{
    int c = blockIdx.x;
    int b = blockIdx.y;
    size_t base = ((size_t)(b * C_ + c)) * T_;
    const float4* a4 = reinterpret_cast<const float4*>(xa + base);
    const float4* b4 = reinterpret_cast<const float4*>(xb + base);

    float s1 = 0.f, s2 = 0.f, s3 = 0.f, s4 = 0.f;
    for (int i = threadIdx.x; i < NV_; i += 256) {
        float4 av = a4[i];
        float4 bv = b4[i];
        float xv[4] = {av.x + bv.x, av.y + bv.y, av.z + bv.z, av.w + bv.w};
        #pragma unroll
        for (int q = 0; q < 4; q++) {
            float x = xv[q];
            float x2 = x * x;
            s1 += x;
            s2 = fmaf(x, x, s2);
            s3 = fmaf(x2, x, s3);
            s4 = fmaf(x2, x2, s4);
        }
    }
    #pragma unroll
    for (int off = 16; off > 0; off >>= 1) {
        s1 += __shfl_down_sync(0xffffffffu, s1, off);
        s2 += __shfl_down_sync(0xffffffffu, s2, off);
        s3 += __shfl_down_sync(0xffffffffu, s3, off);
        s4 += __shfl_down_sync(0xffffffffu, s4, off);
    }
    __shared__ float red[8][4];
    int w = threadIdx.x >> 5;
    if ((threadIdx.x & 31) == 0) {
        red[w][0] = s1; red[w][1] = s2; red[w][2] = s3; red[w][3] = s4;
    }
    __syncthreads();
    if (threadIdx.x == 0) {
        float t1 = 0.f, t2 = 0.f, t3 = 0.f, t4 = 0.f;
        #pragma unroll
        for (int i = 0; i < 8; i++) {
            t1 += red[i][0]; t2 += red[i][1]; t3 += red[i][2]; t4 += red[i][3];
        }
        const float Tf = (float)T_;
        float m  = t1 / Tf;
        float m2 = m * m;
        float sc2 = t2 - t1 * m;                       // sum centered^2
        float var = fmaxf(sc2 / (Tf - 1.0f), 0.f);     // unbiased
        float sd  = sqrtf(var);
        float d   = fmaxf(sd, 0.01f);                  // EPS clamp
        float sc3 = t3 - 3.f * m * t2 + 2.f * Tf * m * m2;
        float sc4 = t4 - 4.f * m * t3 + 6.f * m2 * t2 - 3.f * Tf * m2 * m2;
        float d3inv = 1.f / (Tf * d * d * d);
        float skew = sc3 * d3inv;
        float kurt = sc4 * d3inv / d;
        g_statsT[(c)            * B_ + b] = m;
        g_statsT[(C_ + c)       * B_ + b] = sd;
        g_statsT[(2 * C_ + c)   * B_ + b] = skew;
        g_statsT[(3 * C_ + c)   * B_ + b] = kurt;
    }
}

// ---------------- mini-GEMM: out[r][b] partials = A[r][:K] . xT[:K][b]
// Block: 32 output rows x 32 batch, K-chunk of 128 per blockIdx.y.
// sA stored k-major with pad-36 rows -> inner loop = 1 broadcast LDS.128 +
// 1 conflict-free LDS.32 per k (was 5 scalar LDS).
__device__ __forceinline__ void gemm_tile(
    const float* __restrict__ A, const float* __restrict__ xT,
    float* __restrict__ outP, int K, int rows)
{
    __shared__ __align__(16) float sA[128 * SAP];
    __shared__ float sX[128 * 32];
    int j0 = blockIdx.x * 32;
    int i0 = blockIdx.y * 128;
    int tid = threadIdx.x;

    // global coalesced (consecutive tid -> consecutive k); smem store 4-way conflict (one-time)
    for (int idx = tid; idx < 32 * 128; idx += 256) {
        int jj = idx >> 7;
        int k  = idx & 127;
        sA[k * SAP + jj] = A[(size_t)(j0 + jj) * K + i0 + k];
    }
    for (int idx = tid; idx < 128 * 32; idx += 256)
        sX[idx] = xT[i0 * B_ + idx];
    __syncthreads();

    int b  = tid & 31;
    int jb = (tid >> 5) * 4;     // 8 warps * 4 rows = 32 rows
    float a0 = 0.f, a1 = 0.f, a2 = 0.f, a3 = 0.f;
    #pragma unroll 4
    for (int k = 0; k < 128; k++) {
        float4 av = *reinterpret_cast<const float4*>(&sA[k * SAP + jb]); // broadcast within warp
        float s = sX[k * 32 + b];                                        // lane-distinct banks
        a0 = fmaf(av.x, s, a0);
        a1 = fmaf(av.y, s, a1);
        a2 = fmaf(av.z, s, a2);
        a3 = fmaf(av.w, s, a3);
    }
    size_t obase = (size_t)blockIdx.y * rows * B_ + (size_t)(j0 + jb) * B_ + b;
    outP[obase + 0 * B_] = a0;
    outP[obase + 1 * B_] = a1;
    outP[obase + 2 * B_] = a2;
    outP[obase + 3 * B_] = a3;
}

__global__ __launch_bounds__(256) void gemm1_kernel(const float* __restrict__ W1)
{
    gemm_tile(W1, g_statsT, g_p1, H4C, C_);
}

__global__ __launch_bounds__(256) void reduce1_kernel(const float* __restrict__ b1)
{
    int idx = blockIdx.x * blockDim.x + threadIdx.x;   // over 512*32
    if (idx >= C_ * B_) return;
    float acc = b1[idx >> 5];
    #pragma unroll
    for (int sp = 0; sp < 16; sp++)
        acc += g_p1[sp * (C_ * B_) + idx];
    g_hT[idx] = acc;
}

__global__ __launch_bounds__(256) void gemm2_kernel(const float* __restrict__ W2)
{
    gemm_tile(W2, g_hT, g_p2, C_, 2 * C_);
}

// ---------------- kernel 5: gate reduce + softmax + weighted combine --------
// Blocks enumerate (c,b) in REVERSE order so the first reads hit the L2 tail
// left behind by stats_kernel (L2 = 126MB; pass-1 tail stays resident since
// the mid kernels touch <10MB).
__global__ __launch_bounds__(256) void apply_kernel(
    const float* __restrict__ xa, const float* __restrict__ xb,
    const float* __restrict__ b2, float* __restrict__ out)
{
    int lin = (B_ * C_ - 1) - (int)(blockIdx.y * C_ + blockIdx.x);
    int b = lin / C_;
    int c = lin - b * C_;

    // finish gate GEMM reduction (fixed order) + bias, redundantly per thread
    float s0 = b2[c];
    float s1 = b2[C_ + c];
    #pragma unroll
    for (int sp = 0; sp < 4; sp++) {
        s0 += g_p2[(size_t)sp * (2 * C_ * B_) + (size_t)c * B_ + b];
        s1 += g_p2[(size_t)sp * (2 * C_ * B_) + (size_t)(C_ + c) * B_ + b];
    }
    float mx = fmaxf(s0, s1);
    float e0 = __expf(s0 - mx);
    float e1 = __expf(s1 - mx);
    float inv = 1.f / (e0 + e1);
    float g0 = e0 * inv;
    float g1 = e1 * inv;

    size_t base = ((size_t)(b * C_ + c)) * T_;
    const float4* a4 = reinterpret_cast<const float4*>(xa + base);
    const float4* b4 = reinterpret_cast<const float4*>(xb + base);
    float4* o4 = reinterpret_cast<float4*>(out + base);
    for (int i = threadIdx.x; i < NV_; i += 256) {
        float4 av = a4[i];
        float4 bv = b4[i];
        float4 r;
        r.x = fmaf(av.x, g0, bv.x * g1);
        r.y = fmaf(av.y, g0, bv.y * g1);
        r.z = fmaf(av.z, g0, bv.z * g1);
        r.w = fmaf(av.w, g0, bv.w * g1);
        o4[i] = r;
    }
}

// ---------------- launcher --------------------------------------------------
extern "C" void kernel_launch(void* const* d_in, const int* in_sizes, int n_in,
                              void* d_out, int out_size)
{
    const float* xa = (const float*)d_in[0];
    const float* xb = (const float*)d_in[1];
    const float* W1 = (const float*)d_in[2];
    const float* b1 = (const float*)d_in[3];
    const float* W2 = (const float*)d_in[4];
    const float* b2 = (const float*)d_in[5];
    float* out = (float*)d_out;

    stats_kernel<<<dim3(C_, B_), 256>>>(xa, xb);
    gemm1_kernel<<<dim3(C_ / 32, H4C / 128), 256>>>(W1);          // 16 x 16
    reduce1_kernel<<<(C_ * B_ + 255) / 256, 256>>>(b1);           // 64 blocks
    gemm2_kernel<<<dim3(2 * C_ / 32, C_ / 128), 256>>>(W2);       // 32 x 4
    apply_kernel<<<dim3(C_, B_), 256>>>(xa, xb, b2, out);
}

// round 3
// speedup vs baseline: 1.1220x; 1.0894x over previous
#include <cuda_runtime.h>
#include <math.h>

// Problem constants
#define B_  32
#define C_  512
#define T_  4000
#define NV_ 1000          // T/4 float4s
#define H4C 2048          // 4*C (stats width)
#define SP1 16            // gemm1 K-splits (K=2048, chunk 128)
#define SP2 8             // gemm2 K-splits (K=512,  chunk 64)

// ---------------- scratch (device globals; no allocation allowed) -----------
__device__ float g_statsT[H4C * B_];          // [2048][32]  feature-major, batch=lane
__device__ float g_hT[C_ * B_];               // [512][32]
__device__ float g_p1[SP1 * C_ * B_];         // gemm1 K-split partials
__device__ float g_p2[SP2 * 2 * C_ * B_];     // gemm2 K-split partials

// ---------------- kernel 1: fused add + 4-moment reduction ------------------
__global__ __launch_bounds__(256) void stats_kernel(
    const float* __restrict__ xa, const float* __restrict__ xb)
{
    int c = blockIdx.x;
    int b = blockIdx.y;
    size_t base = ((size_t)(b * C_ + c)) * T_;
    const float4* a4 = reinterpret_cast<const float4*>(xa + base);
    const float4* b4 = reinterpret_cast<const float4*>(xb + base);

    float s1 = 0.f, s2 = 0.f, s3 = 0.f, s4 = 0.f;
    for (int i = threadIdx.x; i < NV_; i += 256) {
        float4 av = a4[i];
        float4 bv = b4[i];
        float xv[4] = {av.x + bv.x, av.y + bv.y, av.z + bv.z, av.w + bv.w};
        #pragma unroll
        for (int q = 0; q < 4; q++) {
            float x = xv[q];
            float x2 = x * x;
            s1 += x;
            s2 = fmaf(x, x, s2);
            s3 = fmaf(x2, x, s3);
            s4 = fmaf(x2, x2, s4);
        }
    }
    #pragma unroll
    for (int off = 16; off > 0; off >>= 1) {
        s1 += __shfl_down_sync(0xffffffffu, s1, off);
        s2 += __shfl_down_sync(0xffffffffu, s2, off);
        s3 += __shfl_down_sync(0xffffffffu, s3, off);
        s4 += __shfl_down_sync(0xffffffffu, s4, off);
    }
    __shared__ float red[8][4];
    int w = threadIdx.x >> 5;
    if ((threadIdx.x & 31) == 0) {
        red[w][0] = s1; red[w][1] = s2; red[w][2] = s3; red[w][3] = s4;
    }
    __syncthreads();
    if (threadIdx.x == 0) {
        float t1 = 0.f, t2 = 0.f, t3 = 0.f, t4 = 0.f;
        #pragma unroll
        for (int i = 0; i < 8; i++) {
            t1 += red[i][0]; t2 += red[i][1]; t3 += red[i][2]; t4 += red[i][3];
        }
        const float Tf = (float)T_;
        float m  = t1 / Tf;
        float m2 = m * m;
        float sc2 = t2 - t1 * m;                       // sum centered^2
        float var = fmaxf(sc2 / (Tf - 1.0f), 0.f);     // unbiased
        float sd  = sqrtf(var);
        float d   = fmaxf(sd, 0.01f);                  // EPS clamp
        float sc3 = t3 - 3.f * m * t2 + 2.f * Tf * m * m2;
        float sc4 = t4 - 4.f * m * t3 + 6.f * m2 * t2 - 3.f * Tf * m2 * m2;
        float d3inv = 1.f / (Tf * d * d * d);
        float skew = sc3 * d3inv;
        float kurt = sc4 * d3inv / d;
        g_statsT[(c)            * B_ + b] = m;
        g_statsT[(C_ + c)       * B_ + b] = sd;
        g_statsT[(2 * C_ + c)   * B_ + b] = skew;
        g_statsT[(3 * C_ + c)   * B_ + b] = kurt;
    }
}

// ---------------- mini-GEMM: out[r][b] partials = A[r][:K] . xT[:K][b]
// Block: 32 output rows x 32 batch, K-chunk KC per blockIdx.y.
// Tile loads: explicit float4 register batches (front-batched LDG.128) then
// conflict-free STS.128. Inner loop: 4 broadcast LDS.128 + 4 scalar LDS.32
// per 4 k-steps.
template<int KC>
__device__ __forceinline__ void gemm_tile(
    const float* __restrict__ A, const float* __restrict__ xT,
    float* __restrict__ outP, int K, int rows)
{
    __shared__ __align__(16) float sA[32 * KC];   // [jj][k] row-major
    __shared__ __align__(16) float sX[KC * 32];   // [k][b]
    const int j0 = blockIdx.x * 32;
    const int i0 = blockIdx.y * KC;
    const int tid = threadIdx.x;

    constexpr int NF = KC / 32;   // float4s per thread for each tile
    float4 va[NF], vx[NF];
    #pragma unroll
    for (int t = 0; t < NF; t++) {
        int f  = tid + t * 256;            // f4 index in [0, 8*KC)
        int jj = f / (KC / 4);
        int kq = f % (KC / 4);
        va[t] = *reinterpret_cast<const float4*>(A + (size_t)(j0 + jj) * K + i0 + 4 * kq);
    }
    {
        const float4* x4 = reinterpret_cast<const float4*>(xT + (size_t)i0 * B_);
        #pragma unroll
        for (int t = 0; t < NF; t++)
            vx[t] = x4[tid + t * 256];
    }
    #pragma unroll
    for (int t = 0; t < NF; t++)
        reinterpret_cast<float4*>(sA)[tid + t * 256] = va[t];
    #pragma unroll
    for (int t = 0; t < NF; t++)
        reinterpret_cast<float4*>(sX)[tid + t * 256] = vx[t];
    __syncthreads();

    const int b  = tid & 31;
    const int jb = (tid >> 5) * 4;     // 8 warps * 4 rows = 32 rows
    float a0 = 0.f, a1 = 0.f, a2 = 0.f, a3 = 0.f;
    #pragma unroll 8
    for (int k4 = 0; k4 < KC / 4; k4++) {
        float4 r0 = reinterpret_cast<const float4*>(sA)[(jb + 0) * (KC / 4) + k4];
        float4 r1 = reinterpret_cast<const float4*>(sA)[(jb + 1) * (KC / 4) + k4];
        float4 r2 = reinterpret_cast<const float4*>(sA)[(jb + 2) * (KC / 4) + k4];
        float4 r3 = reinterpret_cast<const float4*>(sA)[(jb + 3) * (KC / 4) + k4];
        float s0 = sX[(4 * k4 + 0) * 32 + b];
        float s1 = sX[(4 * k4 + 1) * 32 + b];
        float s2 = sX[(4 * k4 + 2) * 32 + b];
        float s3 = sX[(4 * k4 + 3) * 32 + b];
        a0 = fmaf(r0.x, s0, a0); a0 = fmaf(r0.y, s1, a0); a0 = fmaf(r0.z, s2, a0); a0 = fmaf(r0.w, s3, a0);
        a1 = fmaf(r1.x, s0, a1); a1 = fmaf(r1.y, s1, a1); a1 = fmaf(r1.z, s2, a1); a1 = fmaf(r1.w, s3, a1);
        a2 = fmaf(r2.x, s0, a2); a2 = fmaf(r2.y, s1, a2); a2 = fmaf(r2.z, s2, a2); a2 = fmaf(r2.w, s3, a2);
        a3 = fmaf(r3.x, s0, a3); a3 = fmaf(r3.y, s1, a3); a3 = fmaf(r3.z, s2, a3); a3 = fmaf(r3.w, s3, a3);
    }
    size_t obase = (size_t)blockIdx.y * rows * B_ + (size_t)(j0 + jb) * B_ + b;
    outP[obase + 0 * B_] = a0;
    outP[obase + 1 * B_] = a1;
    outP[obase + 2 * B_] = a2;
    outP[obase + 3 * B_] = a3;
}

__global__ __launch_bounds__(256) void gemm1_kernel(const float* __restrict__ W1)
{
    gemm_tile<128>(W1, g_statsT, g_p1, H4C, C_);
}

__global__ __launch_bounds__(256) void reduce1_kernel(const float* __restrict__ b1)
{
    int idx4 = blockIdx.x * 256 + threadIdx.x;    // over C_*B_/4 = 4096 float4s
    if (idx4 >= C_ * B_ / 4) return;
    float bv = b1[idx4 >> 3];                     // 8 f4s (32 scalars) per channel
    float4 acc = make_float4(bv, bv, bv, bv);
    #pragma unroll
    for (int sp = 0; sp < SP1; sp++) {
        float4 p = reinterpret_cast<const float4*>(g_p1)[sp * (C_ * B_ / 4) + idx4];
        acc.x += p.x; acc.y += p.y; acc.z += p.z; acc.w += p.w;
    }
    reinterpret_cast<float4*>(g_hT)[idx4] = acc;
}

__global__ __launch_bounds__(256) void gemm2_kernel(const float* __restrict__ W2)
{
    gemm_tile<64>(W2, g_hT, g_p2, C_, 2 * C_);
}

// ---------------- kernel 5: gate reduce + softmax + weighted combine --------
// Blocks enumerate (c,b) in REVERSE order so the first reads hit the L2 tail
// left behind by stats_kernel.
__global__ __launch_bounds__(256) void apply_kernel(
    const float* __restrict__ xa, const float* __restrict__ xb,
    const float* __restrict__ b2, float* __restrict__ out)
{
    int lin = (B_ * C_ - 1) - (int)(blockIdx.y * C_ + blockIdx.x);
    int b = lin / C_;
    int c = lin - b * C_;

    // finish gate GEMM reduction (fixed order) + bias, redundantly per thread
    float s0 = b2[c];
    float s1 = b2[C_ + c];
    #pragma unroll
    for (int sp = 0; sp < SP2; sp++) {
        s0 += g_p2[(size_t)sp * (2 * C_ * B_) + (size_t)c * B_ + b];
        s1 += g_p2[(size_t)sp * (2 * C_ * B_) + (size_t)(C_ + c) * B_ + b];
    }
    float mx = fmaxf(s0, s1);
    float e0 = __expf(s0 - mx);
    float e1 = __expf(s1 - mx);
    float inv = 1.f / (e0 + e1);
    float g0 = e0 * inv;
    float g1 = e1 * inv;

    size_t base = ((size_t)(b * C_ + c)) * T_;
    const float4* a4 = reinterpret_cast<const float4*>(xa + base);
    const float4* b4 = reinterpret_cast<const float4*>(xb + base);
    float4* o4 = reinterpret_cast<float4*>(out + base);
    for (int i = threadIdx.x; i < NV_; i += 256) {
        float4 av = a4[i];
        float4 bv = b4[i];
        float4 r;
        r.x = fmaf(av.x, g0, bv.x * g1);
        r.y = fmaf(av.y, g0, bv.y * g1);
        r.z = fmaf(av.z, g0, bv.z * g1);
        r.w = fmaf(av.w, g0, bv.w * g1);
        o4[i] = r;
    }
}

// ---------------- launcher --------------------------------------------------
extern "C" void kernel_launch(void* const* d_in, const int* in_sizes, int n_in,
                              void* d_out, int out_size)
{
    const float* xa = (const float*)d_in[0];
    const float* xb = (const float*)d_in[1];
    const float* W1 = (const float*)d_in[2];
    const float* b1 = (const float*)d_in[3];
    const float* W2 = (const float*)d_in[4];
    const float* b2 = (const float*)d_in[5];
    float* out = (float*)d_out;

    stats_kernel<<<dim3(C_, B_), 256>>>(xa, xb);
    gemm1_kernel<<<dim3(C_ / 32, SP1), 256>>>(W1);                // 16 x 16
    reduce1_kernel<<<C_ * B_ / 4 / 256, 256>>>(b1);               // 16 blocks
    gemm2_kernel<<<dim3(2 * C_ / 32, SP2), 256>>>(W2);            // 32 x 8
    apply_kernel<<<dim3(C_, B_), 256>>>(xa, xb, b2, out);
}

// round 4
// speedup vs baseline: 1.1224x; 1.0003x over previous
#include <cuda_runtime.h>
#include <math.h>

// Problem constants
#define B_  32
#define C_  512
#define T_  4000
#define NV_ 1000          // T/4 float4s
#define H4C 2048          // 4*C (stats width)
#define SP1 16            // gemm1 K-splits (K=2048, chunk 128)
#define SP2 8             // gemm2 K-splits (K=512,  chunk 64)

// Weight prefetch (issued by the LAST blocks of stats_kernel):
// W1 = 4MB = 32768 lines of 128B, W2 = 2MB = 16384 lines. 49152 lines total,
// one per thread across the last 192 blocks (192*256 = 49152).
#define PF_BLOCKS 192
#define W1_LINES  32768
#define PF_LINES  49152

// ---------------- scratch (device globals; no allocation allowed) -----------
__device__ float g_statsT[H4C * B_];          // [2048][32]  feature-major, batch=lane
__device__ float g_hT[C_ * B_];               // [512][32]
__device__ float g_p1[SP1 * C_ * B_];         // gemm1 K-split partials
__device__ float g_p2[SP2 * 2 * C_ * B_];     // gemm2 K-split partials

// ---------------- kernel 1: fused add + 4-moment reduction ------------------
__global__ __launch_bounds__(256) void stats_kernel(
    const float* __restrict__ xa, const float* __restrict__ xb,
    const float* __restrict__ W1, const float* __restrict__ W2)
{
    int c = blockIdx.x;
    int b = blockIdx.y;
    size_t base = ((size_t)(b * C_ + c)) * T_;
    const float4* a4 = reinterpret_cast<const float4*>(xa + base);
    const float4* b4 = reinterpret_cast<const float4*>(xb + base);

    float s1 = 0.f, s2 = 0.f, s3 = 0.f, s4 = 0.f;
    for (int i = threadIdx.x; i < NV_; i += 256) {
        float4 av = a4[i];
        float4 bv = b4[i];
        float xv[4] = {av.x + bv.x, av.y + bv.y, av.z + bv.z, av.w + bv.w};
        #pragma unroll
        for (int q = 0; q < 4; q++) {
            float x = xv[q];
            float x2 = x * x;
            s1 += x;
            s2 = fmaf(x, x, s2);
            s3 = fmaf(x2, x, s3);
            s4 = fmaf(x2, x2, s4);
        }
    }

    // L2 warm-up for the GEMM weights: only the tail blocks (scheduled last)
    // prefetch, so the lines survive until gemm1/gemm2 launch.
    {
        int bid = (int)(blockIdx.y * gridDim.x + blockIdx.x);
        int pfb = bid - (B_ * C_ - PF_BLOCKS);
        if (pfb >= 0) {
            int line = pfb * 256 + (int)threadIdx.x;   // [0, PF_LINES)
            const float* p = (line < W1_LINES)
                ? (W1 + (size_t)line * 32)
                : (W2 + (size_t)(line - W1_LINES) * 32);
            asm volatile("prefetch.global.L2 [%0];" :: "l"(p));
        }
    }

    #pragma unroll
    for (int off = 16; off > 0; off >>= 1) {
        s1 += __shfl_down_sync(0xffffffffu, s1, off);
        s2 += __shfl_down_sync(0xffffffffu, s2, off);
        s3 += __shfl_down_sync(0xffffffffu, s3, off);
        s4 += __shfl_down_sync(0xffffffffu, s4, off);
    }
    __shared__ float red[8][4];
    int w = threadIdx.x >> 5;
    if ((threadIdx.x & 31) == 0) {
        red[w][0] = s1; red[w][1] = s2; red[w][2] = s3; red[w][3] = s4;
    }
    __syncthreads();
    if (threadIdx.x == 0) {
        float t1 = 0.f, t2 = 0.f, t3 = 0.f, t4 = 0.f;
        #pragma unroll
        for (int i = 0; i < 8; i++) {
            t1 += red[i][0]; t2 += red[i][1]; t3 += red[i][2]; t4 += red[i][3];
        }
        const float Tf = (float)T_;
        float m  = t1 / Tf;
        float m2 = m * m;
        float sc2 = t2 - t1 * m;                       // sum centered^2
        float var = fmaxf(sc2 / (Tf - 1.0f), 0.f);     // unbiased
        float sd  = sqrtf(var);
        float d   = fmaxf(sd, 0.01f);                  // EPS clamp
        float sc3 = t3 - 3.f * m * t2 + 2.f * Tf * m * m2;
        float sc4 = t4 - 4.f * m * t3 + 6.f * m2 * t2 - 3.f * Tf * m2 * m2;
        float d3inv = 1.f / (Tf * d * d * d);
        float skew = sc3 * d3inv;
        float kurt = sc4 * d3inv / d;
        g_statsT[(c)            * B_ + b] = m;
        g_statsT[(C_ + c)       * B_ + b] = sd;
        g_statsT[(2 * C_ + c)   * B_ + b] = skew;
        g_statsT[(3 * C_ + c)   * B_ + b] = kurt;
    }
}

// ---------------- mini-GEMM: out[r][b] partials = A[r][:K] . xT[:K][b]
// Block: 32 output rows x 32 batch, K-chunk KC per blockIdx.y.
// Tile loads: explicit float4 register batches (front-batched LDG.128) then
// conflict-free STS.128. Inner loop: 4 broadcast LDS.128 + 4 scalar LDS.32
// per 4 k-steps.
template<int KC>
__device__ __forceinline__ void gemm_tile(
    const float* __restrict__ A, const float* __restrict__ xT,
    float* __restrict__ outP, int K, int rows)
{
    __shared__ __align__(16) float sA[32 * KC];   // [jj][k] row-major
    __shared__ __align__(16) float sX[KC * 32];   // [k][b]
    const int j0 = blockIdx.x * 32;
    const int i0 = blockIdx.y * KC;
    const int tid = threadIdx.x;

    constexpr int NF = KC / 32;   // float4s per thread for each tile
    float4 va[NF], vx[NF];
    #pragma unroll
    for (int t = 0; t < NF; t++) {
        int f  = tid + t * 256;            // f4 index in [0, 8*KC)
        int jj = f / (KC / 4);
        int kq = f % (KC / 4);
        va[t] = *reinterpret_cast<const float4*>(A + (size_t)(j0 + jj) * K + i0 + 4 * kq);
    }
    {
        const float4* x4 = reinterpret_cast<const float4*>(xT + (size_t)i0 * B_);
        #pragma unroll
        for (int t = 0; t < NF; t++)
            vx[t] = x4[tid + t * 256];
    }
    #pragma unroll
    for (int t = 0; t < NF; t++)
        reinterpret_cast<float4*>(sA)[tid + t * 256] = va[t];
    #pragma unroll
    for (int t = 0; t < NF; t++)
        reinterpret_cast<float4*>(sX)[tid + t * 256] = vx[t];
    __syncthreads();

    const int b  = tid & 31;
    const int jb = (tid >> 5) * 4;     // 8 warps * 4 rows = 32 rows
    float a0 = 0.f, a1 = 0.f, a2 = 0.f, a3 = 0.f;
    #pragma unroll 8
    for (int k4 = 0; k4 < KC / 4; k4++) {
        float4 r0 = reinterpret_cast<const float4*>(sA)[(jb + 0) * (KC / 4) + k4];
        float4 r1 = reinterpret_cast<const float4*>(sA)[(jb + 1) * (KC / 4) + k4];
        float4 r2 = reinterpret_cast<const float4*>(sA)[(jb + 2) * (KC / 4) + k4];
        float4 r3 = reinterpret_cast<const float4*>(sA)[(jb + 3) * (KC / 4) + k4];
        float s0 = sX[(4 * k4 + 0) * 32 + b];
        float s1 = sX[(4 * k4 + 1) * 32 + b];
        float s2 = sX[(4 * k4 + 2) * 32 + b];
        float s3 = sX[(4 * k4 + 3) * 32 + b];
        a0 = fmaf(r0.x, s0, a0); a0 = fmaf(r0.y, s1, a0); a0 = fmaf(r0.z, s2, a0); a0 = fmaf(r0.w, s3, a0);
        a1 = fmaf(r1.x, s0, a1); a1 = fmaf(r1.y, s1, a1); a1 = fmaf(r1.z, s2, a1); a1 = fmaf(r1.w, s3, a1);
        a2 = fmaf(r2.x, s0, a2); a2 = fmaf(r2.y, s1, a2); a2 = fmaf(r2.z, s2, a2); a2 = fmaf(r2.w, s3, a2);
        a3 = fmaf(r3.x, s0, a3); a3 = fmaf(r3.y, s1, a3); a3 = fmaf(r3.z, s2, a3); a3 = fmaf(r3.w, s3, a3);
    }
    size_t obase = (size_t)blockIdx.y * rows * B_ + (size_t)(j0 + jb) * B_ + b;
    outP[obase + 0 * B_] = a0;
    outP[obase + 1 * B_] = a1;
    outP[obase + 2 * B_] = a2;
    outP[obase + 3 * B_] = a3;
}

__global__ __launch_bounds__(256) void gemm1_kernel(const float* __restrict__ W1)
{
    gemm_tile<128>(W1, g_statsT, g_p1, H4C, C_);
}

__global__ __launch_bounds__(256) void reduce1_kernel(const float* __restrict__ b1)
{
    int idx4 = blockIdx.x * 256 + threadIdx.x;    // over C_*B_/4 = 4096 float4s
    if (idx4 >= C_ * B_ / 4) return;
    float bv = b1[idx4 >> 3];                     // 8 f4s (32 scalars) per channel
    float4 acc = make_float4(bv, bv, bv, bv);
    #pragma unroll
    for (int sp = 0; sp < SP1; sp++) {
        float4 p = reinterpret_cast<const float4*>(g_p1)[sp * (C_ * B_ / 4) + idx4];
        acc.x += p.x; acc.y += p.y; acc.z += p.z; acc.w += p.w;
    }
    reinterpret_cast<float4*>(g_hT)[idx4] = acc;
}

__global__ __launch_bounds__(256) void gemm2_kernel(const float* __restrict__ W2)
{
    gemm_tile<64>(W2, g_hT, g_p2, C_, 2 * C_);
}

// ---------------- kernel 5: gate reduce + softmax + weighted combine --------
// Blocks enumerate (c,b) in REVERSE order so the first reads hit the L2 tail
// left behind by stats_kernel.
__global__ __launch_bounds__(256) void apply_kernel(
    const float* __restrict__ xa, const float* __restrict__ xb,
    const float* __restrict__ b2, float* __restrict__ out)
{
    int lin = (B_ * C_ - 1) - (int)(blockIdx.y * C_ + blockIdx.x);
    int b = lin / C_;
    int c = lin - b * C_;

    // finish gate GEMM reduction (fixed order) + bias, redundantly per thread
    float s0 = b2[c];
    float s1 = b2[C_ + c];
    #pragma unroll
    for (int sp = 0; sp < SP2; sp++) {
        s0 += g_p2[(size_t)sp * (2 * C_ * B_) + (size_t)c * B_ + b];
        s1 += g_p2[(size_t)sp * (2 * C_ * B_) + (size_t)(C_ + c) * B_ + b];
    }
    float mx = fmaxf(s0, s1);
    float e0 = __expf(s0 - mx);
    float e1 = __expf(s1 - mx);
    float inv = 1.f / (e0 + e1);
    float g0 = e0 * inv;
    float g1 = e1 * inv;

    size_t base = ((size_t)(b * C_ + c)) * T_;
    const float4* a4 = reinterpret_cast<const float4*>(xa + base);
    const float4* b4 = reinterpret_cast<const float4*>(xb + base);
    float4* o4 = reinterpret_cast<float4*>(out + base);
    for (int i = threadIdx.x; i < NV_; i += 256) {
        float4 av = a4[i];
        float4 bv = b4[i];
        float4 r;
        r.x = fmaf(av.x, g0, bv.x * g1);
        r.y = fmaf(av.y, g0, bv.y * g1);
        r.z = fmaf(av.z, g0, bv.z * g1);
        r.w = fmaf(av.w, g0, bv.w * g1);
        o4[i] = r;
    }
}

// ---------------- launcher --------------------------------------------------
extern "C" void kernel_launch(void* const* d_in, const int* in_sizes, int n_in,
                              void* d_out, int out_size)
{
    const float* xa = (const float*)d_in[0];
    const float* xb = (const float*)d_in[1];
    const float* W1 = (const float*)d_in[2];
    const float* b1 = (const float*)d_in[3];
    const float* W2 = (const float*)d_in[4];
    const float* b2 = (const float*)d_in[5];
    float* out = (float*)d_out;

    stats_kernel<<<dim3(C_, B_), 256>>>(xa, xb, W1, W2);
    gemm1_kernel<<<dim3(C_ / 32, SP1), 256>>>(W1);                // 16 x 16
    reduce1_kernel<<<C_ * B_ / 4 / 256, 256>>>(b1);               // 16 blocks
    gemm2_kernel<<<dim3(2 * C_ / 32, SP2), 256>>>(W2);            // 32 x 8
    apply_kernel<<<dim3(C_, B_), 256>>>(xa, xb, b2, out);
}